// round 6
// baseline (speedup 1.0000x reference)
#include <cuda_runtime.h>
#include <cuda_fp16.h>
#include <cstdint>

// ===================== problem constants =====================
#define U_DIM   14336
#define K_DIM   4096
#define NB      32
#define TILE_M  128
#define NCTA    (U_DIM / TILE_M)     // 112
#define NCHUNK  (K_DIM / 64)         // 64 chunks of 64 k-values
#define CLIPV   100.0f
// PRMT LUT bytes: crumb 0->0x00, 1->0x3C (+1 fp16 hi), 2->0xBC (-1), 3->0x00
#define HI_LUT  0x00BC3C00u

// x transposed to [K][N] fp16 (written by pre-kernel)
__device__ __half g_xt[K_DIM * NB];

// ===================== helpers =====================
__device__ __forceinline__ uint32_t prmt(uint32_t a, uint32_t b, uint32_t s) {
    uint32_t r; asm("prmt.b32 %0,%1,%2,%3;" : "=r"(r) : "r"(a), "r"(b), "r"(s)); return r;
}
__device__ __forceinline__ uint32_t smem_u32(const void* p) {
    uint32_t a;
    asm("{ .reg .u64 t; cvta.to.shared.u64 t, %1; cvt.u32.u64 %0, t; }" : "=r"(a) : "l"(p));
    return a;
}
// merge 4 int32 (one crumb-byte each, low byte) -> one 32-bit word of 16 crumbs
__device__ __forceinline__ uint32_t mergew(uint4 q) {
    return prmt(prmt(q.x, q.y, 0x0040), prmt(q.z, q.w, 0x0040), 0x5410);
}
// decode: from 16-crumb word w, lane's quad q=lane&3 (sh=4q) extract crumbs
// (2q,2q+1) -> lo (fp16x2) and (2q+8,2q+9) -> hi (fp16x2)
__device__ __forceinline__ void dec(uint32_t w, uint32_t sh, uint32_t& lo, uint32_t& hi) {
    uint32_t t   = w >> sh;
    uint32_t x   = t & 0x000F000Fu;
    uint32_t z   = x | (x << 2);
    uint32_t sel = (z & 0x33u) | ((z >> 8) & 0x3300u);
    uint32_t h   = prmt(HI_LUT, 0u, sel);   // bytes = hi-bytes of the 4 fp16 values
    lo = prmt(h, 0u, 0x1404u);              // {0,h0,0,h1}
    hi = prmt(h, 0u, 0x3424u);              // {0,h2,0,h3}
}
__device__ __forceinline__ void mma16816(float* c,
        uint32_t a0, uint32_t a1, uint32_t a2, uint32_t a3,
        uint32_t b0, uint32_t b1) {
    asm volatile(
        "mma.sync.aligned.m16n8k16.row.col.f32.f16.f16.f32 "
        "{%0,%1,%2,%3},{%4,%5,%6,%7},{%8,%9},{%0,%1,%2,%3};"
        : "+f"(c[0]), "+f"(c[1]), "+f"(c[2]), "+f"(c[3])
        : "r"(a0), "r"(a1), "r"(a2), "r"(a3), "r"(b0), "r"(b1));
}
__device__ __forceinline__ void ldsm4t(uint32_t addr,
        uint32_t& r0, uint32_t& r1, uint32_t& r2, uint32_t& r3) {
    asm volatile("ldmatrix.sync.aligned.m8n8.x4.trans.shared.b16 {%0,%1,%2,%3}, [%4];"
        : "=r"(r0), "=r"(r1), "=r"(r2), "=r"(r3) : "r"(addr));
}

// ===================== pre-kernel: x[N][K] f32 -> g_xt[K][N] f16 =====================
__global__ void xt_kernel(const float* __restrict__ x) {
    int i = blockIdx.x * blockDim.x + threadIdx.x;  // = k*32 + n
    int k = i >> 5, n = i & 31;
    g_xt[i] = __float2half_rn(x[n * K_DIM + k]);
}

// ===================== main GEMM =====================
// 112 CTAs x 128 threads; 4 warps, each m32 x n32; K in 64-wide chunks
#define BROW 80          // padded bytes per k-row in smem B tile (64B data + 16 pad)
#define BBUF (64 * BROW) // 5120 B per ring slot

__global__ void __launch_bounds__(128, 1)
ternary_hmma_kernel(const int* __restrict__ pw,
                    const float* __restrict__ scale,
                    const float* __restrict__ bias,
                    float* __restrict__ out) {
    __shared__ __align__(16) uint8_t sBB[4][BBUF];   // 20 KB ring of B tiles [k][n]

    const int tid  = threadIdx.x;
    const int lane = tid & 31;
    const int wid  = tid >> 5;
    const int u0   = blockIdx.x * TILE_M;
    const uint32_t sh = (lane & 3) * 4;

    // lane owns weight row u0 + wid*32 + lane
    const int urow = u0 + wid * 32 + lane;
    const uint4* pwq = reinterpret_cast<const uint4*>(pw + (size_t)urow * (K_DIM / 4));

    // B staging task: thread -> (k-row, 32B segment)
    const int bk   = tid >> 1;
    const int bseg = tid & 1;
    const uint8_t* xtb = reinterpret_cast<const uint8_t*>(g_xt);
    const uint32_t sB0 = smem_u32(sBB);
    uint8_t* sB = reinterpret_cast<uint8_t*>(sBB);

    // ldmatrix per-lane offset: krow = lane&15, ntile-pair select = lane>>4
    const uint32_t ld_off = (uint32_t)((lane & 15) * BROW + (lane >> 4) * 16);

    float acc[2][4][4];
#pragma unroll
    for (int a = 0; a < 2; ++a)
#pragma unroll
        for (int t = 0; t < 4; ++t)
#pragma unroll
            for (int j = 0; j < 4; ++j) acc[a][t][j] = 0.0f;

    // ---- prologue ----
    uint4 raw[4][4];
#pragma unroll
    for (int s = 0; s < 4; ++s)
#pragma unroll
        for (int i = 0; i < 4; ++i) raw[s][i] = pwq[s * 4 + i];

    // stage B chunks 0,1 straight into slots 0,1; prefetch chunk 2 into regs
    uint4 bv0, bv1;
#pragma unroll
    for (int cc = 0; cc < 2; ++cc) {
        uint4 v0 = *reinterpret_cast<const uint4*>(xtb + (size_t)(cc * 64 + bk) * 64 + bseg * 32);
        uint4 v1 = *reinterpret_cast<const uint4*>(xtb + (size_t)(cc * 64 + bk) * 64 + bseg * 32 + 16);
        *reinterpret_cast<uint4*>(sB + cc * BBUF + bk * BROW + bseg * 32)      = v0;
        *reinterpret_cast<uint4*>(sB + cc * BBUF + bk * BROW + bseg * 32 + 16) = v1;
    }
    bv0 = *reinterpret_cast<const uint4*>(xtb + (size_t)(2 * 64 + bk) * 64 + bseg * 32);
    bv1 = *reinterpret_cast<const uint4*>(xtb + (size_t)(2 * 64 + bk) * 64 + bseg * 32 + 16);
    __syncthreads();

    // ---- main loop ----
#pragma unroll 4
    for (int c = 0; c < NCHUNK; ++c) {
        const int s = c & 3;
        // merge current chunk's crumb words (row = lane)
        uint32_t wk0 = mergew(raw[s][0]);
        uint32_t wk1 = mergew(raw[s][1]);
        uint32_t wk2 = mergew(raw[s][2]);
        uint32_t wk3 = mergew(raw[s][3]);
        // prefetch pw chunk c+4 into freed slot
        {
            int pc = (c + 4 < NCHUNK) ? (c + 4) : (NCHUNK - 1);
#pragma unroll
            for (int i = 0; i < 4; ++i) raw[s][i] = pwq[pc * 4 + i];
        }
        // stage B chunk c+2 (from bv regs), prefetch chunk c+3
        {
            int wslot = (c + 2) & 3;
            *reinterpret_cast<uint4*>(sB + wslot * BBUF + bk * BROW + bseg * 32)      = bv0;
            *reinterpret_cast<uint4*>(sB + wslot * BBUF + bk * BROW + bseg * 32 + 16) = bv1;
            int bc = (c + 3 < NCHUNK) ? (c + 3) : (NCHUNK - 1);
            bv0 = *reinterpret_cast<const uint4*>(xtb + (size_t)(bc * 64 + bk) * 64 + bseg * 32);
            bv1 = *reinterpret_cast<const uint4*>(xtb + (size_t)(bc * 64 + bk) * 64 + bseg * 32 + 16);
        }
        __syncthreads();

        // compute on sBB[c&3] and wk*
        const uint32_t bbase = sB0 + (uint32_t)(c & 3) * BBUF + ld_off;
        uint32_t wks[4] = { wk0, wk1, wk2, wk3 };
#pragma unroll
        for (int ks = 0; ks < 4; ++ks) {
            uint32_t b0, b1, b2, b3, b4, b5, b6, b7;
            ldsm4t(bbase + ks * (16 * BROW),      b0, b1, b2, b3);   // ntiles 0,1
            ldsm4t(bbase + ks * (16 * BROW) + 32, b4, b5, b6, b7);   // ntiles 2,3
            uint32_t wv = wks[ks];
            const int rb = lane >> 2;
#pragma unroll
            for (int af = 0; af < 2; ++af) {
                uint32_t wlo = (uint32_t)__shfl_sync(0xffffffffu, (int)wv, rb + af * 16);
                uint32_t whi = (uint32_t)__shfl_sync(0xffffffffu, (int)wv, rb + af * 16 + 8);
                uint32_t a0, a1, a2, a3;
                dec(wlo, sh, a0, a2);
                dec(whi, sh, a1, a3);
                mma16816(acc[af][0], a0, a1, a2, a3, b0, b1);
                mma16816(acc[af][1], a0, a1, a2, a3, b2, b3);
                mma16816(acc[af][2], a0, a1, a2, a3, b4, b5);
                mma16816(acc[af][3], a0, a1, a2, a3, b6, b7);
            }
        }
    }

    // ---- epilogue: scale/bias/clip, write out [N][U] ----
    const int rb = lane >> 2;
#pragma unroll
    for (int af = 0; af < 2; ++af) {
        const int ua = u0 + wid * 32 + af * 16 + rb;
        const int ub = ua + 8;
        const float sa  = scale[ua], ba = bias[ua];
        const float sbv = scale[ub], bb = bias[ub];
#pragma unroll
        for (int nt = 0; nt < 4; ++nt) {
            const int n0 = nt * 8 + (lane & 3) * 2;
            float y0 = fminf(fmaxf(acc[af][nt][0] * sa + ba, -CLIPV), CLIPV);
            float y1 = fminf(fmaxf(acc[af][nt][1] * sa + ba, -CLIPV), CLIPV);
            float y2 = fminf(fmaxf(acc[af][nt][2] * sbv + bb, -CLIPV), CLIPV);
            float y3 = fminf(fmaxf(acc[af][nt][3] * sbv + bb, -CLIPV), CLIPV);
            out[(size_t)n0 * U_DIM + ua]       = y0;
            out[(size_t)(n0 + 1) * U_DIM + ua] = y1;
            out[(size_t)n0 * U_DIM + ub]       = y2;
            out[(size_t)(n0 + 1) * U_DIM + ub] = y3;
        }
    }
}

// ===================== launch =====================
extern "C" void kernel_launch(void* const* d_in, const int* in_sizes, int n_in,
                              void* d_out, int out_size) {
    const float* x     = (const float*)d_in[0];
    const int*   pw    = (const int*)d_in[1];
    const float* scale = (const float*)d_in[2];
    const float* bias  = (const float*)d_in[3];
    float*       out   = (float*)d_out;

    xt_kernel<<<(K_DIM * NB) / 256, 256>>>(x);
    ternary_hmma_kernel<<<NCTA, 128>>>(pw, scale, bias, out);
}

// round 7
// speedup vs baseline: 1.2320x; 1.2320x over previous
#include <cuda_runtime.h>
#include <cuda_fp16.h>
#include <cstdint>

// ===================== problem constants =====================
#define U_DIM   14336
#define K_DIM   4096
#define NB      32
#define TILE_M  128
#define NCTA_U  (U_DIM / TILE_M)     // 112
#define NCHUNK  (K_DIM / 64)         // 64 chunks of 64 k-values
#define NSPLIT  4
#define NCHUNK_Q (NCHUNK / NSPLIT)   // 16 chunks per CTA
#define CLIPV   100.0f
// PRMT LUT bytes: crumb 0->0x00, 1->0x3C (+1 fp16 hi), 2->0xBC (-1), 3->0x00
#define HI_LUT  0x00BC3C00u

// x transposed to [K][N] fp16 (written by pre-kernel)
__device__ __half g_xt[K_DIM * NB];
// split-K fp32 partials: [split][n][u]
__device__ float  g_part[NSPLIT * NB * U_DIM];

// ===================== helpers =====================
__device__ __forceinline__ uint32_t prmt(uint32_t a, uint32_t b, uint32_t s) {
    uint32_t r; asm("prmt.b32 %0,%1,%2,%3;" : "=r"(r) : "r"(a), "r"(b), "r"(s)); return r;
}
__device__ __forceinline__ uint32_t smem_u32(const void* p) {
    uint32_t a;
    asm("{ .reg .u64 t; cvta.to.shared.u64 t, %1; cvt.u32.u64 %0, t; }" : "=r"(a) : "l"(p));
    return a;
}
// merge 4 int32 (one crumb-byte each, low byte) -> one 32-bit word of 16 crumbs
__device__ __forceinline__ uint32_t mergew(uint4 q) {
    return prmt(prmt(q.x, q.y, 0x0040), prmt(q.z, q.w, 0x0040), 0x5410);
}
// decode: from 16-crumb word w, lane's quad q=lane&3 (sh=4q) extract crumbs
// (2q,2q+1) -> lo (fp16x2) and (2q+8,2q+9) -> hi (fp16x2)
__device__ __forceinline__ void dec(uint32_t w, uint32_t sh, uint32_t& lo, uint32_t& hi) {
    uint32_t t   = w >> sh;
    uint32_t x   = t & 0x000F000Fu;
    uint32_t z   = x | (x << 2);
    uint32_t sel = (z & 0x33u) | ((z >> 8) & 0x3300u);
    uint32_t h   = prmt(HI_LUT, 0u, sel);   // bytes = hi-bytes of the 4 fp16 values
    lo = prmt(h, 0u, 0x1404u);              // {0,h0,0,h1}
    hi = prmt(h, 0u, 0x3424u);              // {0,h2,0,h3}
}
__device__ __forceinline__ void mma16816(float* c,
        uint32_t a0, uint32_t a1, uint32_t a2, uint32_t a3,
        uint32_t b0, uint32_t b1) {
    asm volatile(
        "mma.sync.aligned.m16n8k16.row.col.f32.f16.f16.f32 "
        "{%0,%1,%2,%3},{%4,%5,%6,%7},{%8,%9},{%0,%1,%2,%3};"
        : "+f"(c[0]), "+f"(c[1]), "+f"(c[2]), "+f"(c[3])
        : "r"(a0), "r"(a1), "r"(a2), "r"(a3), "r"(b0), "r"(b1));
}
__device__ __forceinline__ void ldsm4t(uint32_t addr,
        uint32_t& r0, uint32_t& r1, uint32_t& r2, uint32_t& r3) {
    asm volatile("ldmatrix.sync.aligned.m8n8.x4.trans.shared.b16 {%0,%1,%2,%3}, [%4];"
        : "=r"(r0), "=r"(r1), "=r"(r2), "=r"(r3) : "r"(addr));
}

// ===================== pre-kernel: x[N][K] f32 -> g_xt[K][N] f16 =====================
__global__ void xt_kernel(const float* __restrict__ x) {
    int i = blockIdx.x * blockDim.x + threadIdx.x;  // = k*32 + n
    int k = i >> 5, n = i & 31;
    g_xt[i] = __float2half_rn(x[n * K_DIM + k]);
}

// ===================== main GEMM =====================
// 448 CTAs x 128 threads; CTA = (u-tile, K-quarter); 4 warps, each m32 x n32
#define BROW 80          // padded bytes per k-row in smem B tile (64B data + 16 pad)
#define BBUF (64 * BROW) // 5120 B per ring slot

__global__ void __launch_bounds__(128, 3)
ternary_hmma_kernel(const int* __restrict__ pw) {
    __shared__ __align__(16) uint8_t sBB[4][BBUF];   // 20 KB ring of B tiles [k][n]

    const int tid  = threadIdx.x;
    const int lane = tid & 31;
    const int wid  = tid >> 5;
    const int bu   = blockIdx.x >> 2;        // u-tile index   (0..111)
    const int sq   = blockIdx.x & 3;         // K-quarter      (0..3)
    const int u0   = bu * TILE_M;
    const int c0   = sq * NCHUNK_Q;          // first chunk (multiple of 4 -> ring aligned)
    const int cEnd = c0 + NCHUNK_Q;
    const uint32_t sh = (lane & 3) * 4;

    // lane owns weight row u0 + wid*32 + lane
    const int urow = u0 + wid * 32 + lane;
    const uint4* pwq = reinterpret_cast<const uint4*>(pw + (size_t)urow * (K_DIM / 4));

    // B staging task: thread -> (k-row, 32B segment)
    const int bk   = tid >> 1;
    const int bseg = tid & 1;
    const uint8_t* xtb = reinterpret_cast<const uint8_t*>(g_xt);
    const uint32_t sB0 = smem_u32(sBB);
    uint8_t* sB = reinterpret_cast<uint8_t*>(sBB);

    // ldmatrix per-lane offset: krow = lane&15, ntile-pair select = lane>>4
    const uint32_t ld_off = (uint32_t)((lane & 15) * BROW + (lane >> 4) * 16);

    float acc[2][4][4];
#pragma unroll
    for (int a = 0; a < 2; ++a)
#pragma unroll
        for (int t = 0; t < 4; ++t)
#pragma unroll
            for (int j = 0; j < 4; ++j) acc[a][t][j] = 0.0f;

    // ---- prologue: prefetch pw chunks c0..c0+3, stage B c0,c0+1, reg-hold c0+2 ----
    uint4 raw[4][4];
#pragma unroll
    for (int s = 0; s < 4; ++s)
#pragma unroll
        for (int i = 0; i < 4; ++i) raw[s][i] = pwq[(c0 + s) * 4 + i];

    uint4 bv0, bv1;
#pragma unroll
    for (int cc = 0; cc < 2; ++cc) {
        uint4 v0 = *reinterpret_cast<const uint4*>(xtb + (size_t)((c0 + cc) * 64 + bk) * 64 + bseg * 32);
        uint4 v1 = *reinterpret_cast<const uint4*>(xtb + (size_t)((c0 + cc) * 64 + bk) * 64 + bseg * 32 + 16);
        *reinterpret_cast<uint4*>(sB + cc * BBUF + bk * BROW + bseg * 32)      = v0;
        *reinterpret_cast<uint4*>(sB + cc * BBUF + bk * BROW + bseg * 32 + 16) = v1;
    }
    bv0 = *reinterpret_cast<const uint4*>(xtb + (size_t)((c0 + 2) * 64 + bk) * 64 + bseg * 32);
    bv1 = *reinterpret_cast<const uint4*>(xtb + (size_t)((c0 + 2) * 64 + bk) * 64 + bseg * 32 + 16);
    __syncthreads();

    // ---- main loop over this CTA's 16 chunks ----
#pragma unroll 4
    for (int c = c0; c < cEnd; ++c) {
        const int s = c & 3;
        // merge current chunk's crumb words (row = lane)
        uint32_t wk0 = mergew(raw[s][0]);
        uint32_t wk1 = mergew(raw[s][1]);
        uint32_t wk2 = mergew(raw[s][2]);
        uint32_t wk3 = mergew(raw[s][3]);
        // prefetch pw chunk c+4 into freed slot
        {
            int pc = (c + 4 < cEnd) ? (c + 4) : (cEnd - 1);
#pragma unroll
            for (int i = 0; i < 4; ++i) raw[s][i] = pwq[pc * 4 + i];
        }
        // stage B chunk c+2 (from bv regs), prefetch chunk c+3
        {
            int wslot = (c + 2) & 3;
            *reinterpret_cast<uint4*>(sB + wslot * BBUF + bk * BROW + bseg * 32)      = bv0;
            *reinterpret_cast<uint4*>(sB + wslot * BBUF + bk * BROW + bseg * 32 + 16) = bv1;
            int bc = (c + 3 < cEnd) ? (c + 3) : (cEnd - 1);
            bv0 = *reinterpret_cast<const uint4*>(xtb + (size_t)(bc * 64 + bk) * 64 + bseg * 32);
            bv1 = *reinterpret_cast<const uint4*>(xtb + (size_t)(bc * 64 + bk) * 64 + bseg * 32 + 16);
        }
        __syncthreads();

        // compute on sBB[c&3] and wk*
        const uint32_t bbase = sB0 + (uint32_t)(c & 3) * BBUF + ld_off;
        uint32_t wks[4] = { wk0, wk1, wk2, wk3 };
#pragma unroll
        for (int ks = 0; ks < 4; ++ks) {
            uint32_t b0, b1, b2, b3, b4, b5, b6, b7;
            ldsm4t(bbase + ks * (16 * BROW),      b0, b1, b2, b3);   // ntiles 0,1
            ldsm4t(bbase + ks * (16 * BROW) + 32, b4, b5, b6, b7);   // ntiles 2,3
            uint32_t wv = wks[ks];
            const int rb = lane >> 2;
#pragma unroll
            for (int af = 0; af < 2; ++af) {
                uint32_t wlo = (uint32_t)__shfl_sync(0xffffffffu, (int)wv, rb + af * 16);
                uint32_t whi = (uint32_t)__shfl_sync(0xffffffffu, (int)wv, rb + af * 16 + 8);
                uint32_t a0, a1, a2, a3;
                dec(wlo, sh, a0, a2);
                dec(whi, sh, a1, a3);
                mma16816(acc[af][0], a0, a1, a2, a3, b0, b1);
                mma16816(acc[af][1], a0, a1, a2, a3, b2, b3);
                mma16816(acc[af][2], a0, a1, a2, a3, b4, b5);
                mma16816(acc[af][3], a0, a1, a2, a3, b6, b7);
            }
        }
    }

    // ---- epilogue: write raw fp32 partials for this K-quarter ----
    float* pout = g_part + (size_t)sq * NB * U_DIM;
    const int rb = lane >> 2;
#pragma unroll
    for (int af = 0; af < 2; ++af) {
        const int ua = u0 + wid * 32 + af * 16 + rb;
        const int ub = ua + 8;
#pragma unroll
        for (int nt = 0; nt < 4; ++nt) {
            const int n0 = nt * 8 + (lane & 3) * 2;
            pout[(size_t)n0 * U_DIM + ua]       = acc[af][nt][0];
            pout[(size_t)(n0 + 1) * U_DIM + ua] = acc[af][nt][1];
            pout[(size_t)n0 * U_DIM + ub]       = acc[af][nt][2];
            pout[(size_t)(n0 + 1) * U_DIM + ub] = acc[af][nt][3];
        }
    }
}

// ===================== combine: sum partials, scale/bias/clip =====================
__global__ void __launch_bounds__(256)
combine_kernel(const float* __restrict__ scale,
               const float* __restrict__ bias,
               float* __restrict__ out) {
    int i = blockIdx.x * blockDim.x + threadIdx.x;   // = n*U_DIM + u
    int u = i % U_DIM;
    float s = g_part[i]
            + g_part[(size_t)NB * U_DIM + i]
            + g_part[(size_t)2 * NB * U_DIM + i]
            + g_part[(size_t)3 * NB * U_DIM + i];
    float y = s * scale[u] + bias[u];
    out[i] = fminf(fmaxf(y, -CLIPV), CLIPV);
}

// ===================== launch =====================
extern "C" void kernel_launch(void* const* d_in, const int* in_sizes, int n_in,
                              void* d_out, int out_size) {
    const float* x     = (const float*)d_in[0];
    const int*   pw    = (const int*)d_in[1];
    const float* scale = (const float*)d_in[2];
    const float* bias  = (const float*)d_in[3];
    float*       out   = (float*)d_out;

    xt_kernel<<<(K_DIM * NB) / 256, 256>>>(x);
    ternary_hmma_kernel<<<NCTA_U * NSPLIT, 128>>>(pw);
    combine_kernel<<<(NB * U_DIM) / 256, 256>>>(scale, bias, out);
}

// round 9
// speedup vs baseline: 2.0237x; 1.6427x over previous
#include <cuda_runtime.h>
#include <cuda_fp16.h>
#include <cstdint>

// ===================== problem constants =====================
#define U_DIM   14336
#define K_DIM   4096
#define NB      32
#define TILE_M  128
#define NCTA_U  (U_DIM / TILE_M)     // 112
#define NCHUNK  (K_DIM / 64)         // 64 chunks of 64 k-values
#define NSPLIT  4
#define NCHUNK_Q (NCHUNK / NSPLIT)   // 16 chunks per CTA
#define CLIPV   100.0f
// PRMT LUT bytes: crumb 0->0x00, 1->0x3C (+1 fp16 hi), 2->0xBC (-1), 3->0x00
#define HI_LUT  0x00BC3C00u

// x transposed to [K][N] fp16 (written by pre-kernel)
__device__ __half g_xt[K_DIM * NB];
// split-K fp32 partials: [split][n][u]
__device__ float  g_part[NSPLIT * NB * U_DIM];

// ===================== helpers =====================
__device__ __forceinline__ uint32_t prmt(uint32_t a, uint32_t b, uint32_t s) {
    uint32_t r; asm("prmt.b32 %0,%1,%2,%3;" : "=r"(r) : "r"(a), "r"(b), "r"(s)); return r;
}
__device__ __forceinline__ uint32_t smem_u32(const void* p) {
    uint32_t a;
    asm("{ .reg .u64 t; cvta.to.shared.u64 t, %1; cvt.u32.u64 %0, t; }" : "=r"(a) : "l"(p));
    return a;
}
// merge 4 int32 (one crumb-byte each, low byte) -> one 32-bit word of 16 crumbs
__device__ __forceinline__ uint32_t mergew(uint4 q) {
    return prmt(prmt(q.x, q.y, 0x0040), prmt(q.z, q.w, 0x0040), 0x5410);
}
// decode: from 16-crumb word w, lane's quad q=lane&3 (sh=4q) extract crumbs
// (2q,2q+1) -> lo (fp16x2) and (2q+8,2q+9) -> hi (fp16x2)
__device__ __forceinline__ void dec(uint32_t w, uint32_t sh, uint32_t& lo, uint32_t& hi) {
    uint32_t t   = w >> sh;
    uint32_t x   = t & 0x000F000Fu;
    uint32_t z   = x | (x << 2);
    uint32_t sel = (z & 0x33u) | ((z >> 8) & 0x3300u);
    uint32_t h   = prmt(HI_LUT, 0u, sel);   // bytes = hi-bytes of the 4 fp16 values
    lo = prmt(h, 0u, 0x1404u);              // {0,h0,0,h1}
    hi = prmt(h, 0u, 0x3424u);              // {0,h2,0,h3}
}
__device__ __forceinline__ void mma16816(float* c,
        uint32_t a0, uint32_t a1, uint32_t a2, uint32_t a3,
        uint32_t b0, uint32_t b1) {
    asm volatile(
        "mma.sync.aligned.m16n8k16.row.col.f32.f16.f16.f32 "
        "{%0,%1,%2,%3},{%4,%5,%6,%7},{%8,%9},{%0,%1,%2,%3};"
        : "+f"(c[0]), "+f"(c[1]), "+f"(c[2]), "+f"(c[3])
        : "r"(a0), "r"(a1), "r"(a2), "r"(a3), "r"(b0), "r"(b1));
}
__device__ __forceinline__ void ldsm4t(uint32_t addr,
        uint32_t& r0, uint32_t& r1, uint32_t& r2, uint32_t& r3) {
    asm volatile("ldmatrix.sync.aligned.m8n8.x4.trans.shared.b16 {%0,%1,%2,%3}, [%4];"
        : "=r"(r0), "=r"(r1), "=r"(r2), "=r"(r3) : "r"(addr));
}

// ===================== pre-kernel: x[N][K] f32 -> g_xt[K][N] f16 (tiled transpose) =====================
// block = 256 threads handles a 32k x 32n tile; both gmem sides coalesced
__global__ void __launch_bounds__(256)
xt_kernel(const float* __restrict__ x) {
    __shared__ __half s[32][33];
    const int k0 = blockIdx.x * 32;
    const int t  = threadIdx.x;
    const int n_r = t >> 3;              // 0..31
    const int kq  = (t & 7) * 4;         // 0,4,..,28
    float4 v = *reinterpret_cast<const float4*>(x + (size_t)n_r * K_DIM + k0 + kq);
    s[kq + 0][n_r] = __float2half_rn(v.x);
    s[kq + 1][n_r] = __float2half_rn(v.y);
    s[kq + 2][n_r] = __float2half_rn(v.z);
    s[kq + 3][n_r] = __float2half_rn(v.w);
    __syncthreads();
    const int k_w = t >> 3;              // 0..31
    const int nq  = (t & 7) * 4;         // 0,4,..,28
    __half2 a = __halves2half2(s[k_w][nq],     s[k_w][nq + 1]);
    __half2 b = __halves2half2(s[k_w][nq + 2], s[k_w][nq + 3]);
    __half* dst = g_xt + (size_t)(k0 + k_w) * NB + nq;
    *reinterpret_cast<__half2*>(dst)     = a;
    *reinterpret_cast<__half2*>(dst + 2) = b;
}

// ===================== main GEMM =====================
// 448 CTAs x 128 threads; CTA = (u-tile, K-quarter); 4 warps, each m32 x n32
// occupancy 4 -> grid 448 fits in ONE wave (148*4 = 592)
#define BROW 80          // padded bytes per k-row in smem B tile (64B data + 16 pad)
#define BBUF (64 * BROW) // 5120 B per ring slot

__global__ void __launch_bounds__(128, 4)
ternary_hmma_kernel(const int* __restrict__ pw) {
    __shared__ __align__(16) uint8_t sBB[4][BBUF];   // 20 KB ring of B tiles [k][n]

    const int tid  = threadIdx.x;
    const int lane = tid & 31;
    const int wid  = tid >> 5;
    const int bu   = blockIdx.x >> 2;        // u-tile index   (0..111)
    const int sq   = blockIdx.x & 3;         // K-quarter      (0..3)
    const int u0   = bu * TILE_M;
    const int c0   = sq * NCHUNK_Q;          // first chunk (multiple of 4 -> ring aligned)
    const int cEnd = c0 + NCHUNK_Q;
    const uint32_t sh = (lane & 3) * 4;

    // lane owns weight row u0 + wid*32 + lane
    const int urow = u0 + wid * 32 + lane;
    const uint4* pwq = reinterpret_cast<const uint4*>(pw + (size_t)urow * (K_DIM / 4));

    // B staging task: thread -> (k-row, 32B segment)
    const int bk   = tid >> 1;
    const int bseg = tid & 1;
    const uint8_t* xtb = reinterpret_cast<const uint8_t*>(g_xt);
    const uint32_t sB0 = smem_u32(sBB);
    uint8_t* sB = reinterpret_cast<uint8_t*>(sBB);

    // ldmatrix per-lane offset: krow = lane&15, ntile-pair select = lane>>4
    const uint32_t ld_off = (uint32_t)((lane & 15) * BROW + (lane >> 4) * 16);

    float acc[2][4][4];
#pragma unroll
    for (int a = 0; a < 2; ++a)
#pragma unroll
        for (int t = 0; t < 4; ++t)
#pragma unroll
            for (int j = 0; j < 4; ++j) acc[a][t][j] = 0.0f;

    // ---- prologue: pw prefetch ring depth 2; stage B c0,c0+1, reg-hold c0+2 ----
    uint4 raw[2][4];
#pragma unroll
    for (int s = 0; s < 2; ++s)
#pragma unroll
        for (int i = 0; i < 4; ++i) raw[s][i] = pwq[(c0 + s) * 4 + i];

    uint4 bv0, bv1;
#pragma unroll
    for (int cc = 0; cc < 2; ++cc) {
        uint4 v0 = *reinterpret_cast<const uint4*>(xtb + (size_t)((c0 + cc) * 64 + bk) * 64 + bseg * 32);
        uint4 v1 = *reinterpret_cast<const uint4*>(xtb + (size_t)((c0 + cc) * 64 + bk) * 64 + bseg * 32 + 16);
        *reinterpret_cast<uint4*>(sB + cc * BBUF + bk * BROW + bseg * 32)      = v0;
        *reinterpret_cast<uint4*>(sB + cc * BBUF + bk * BROW + bseg * 32 + 16) = v1;
    }
    bv0 = *reinterpret_cast<const uint4*>(xtb + (size_t)((c0 + 2) * 64 + bk) * 64 + bseg * 32);
    bv1 = *reinterpret_cast<const uint4*>(xtb + (size_t)((c0 + 2) * 64 + bk) * 64 + bseg * 32 + 16);
    __syncthreads();

    // ---- main loop over this CTA's 16 chunks ----
#pragma unroll 4
    for (int c = c0; c < cEnd; ++c) {
        const int s = c & 1;
        // merge current chunk's crumb words (row = lane)
        uint32_t wk0 = mergew(raw[s][0]);
        uint32_t wk1 = mergew(raw[s][1]);
        uint32_t wk2 = mergew(raw[s][2]);
        uint32_t wk3 = mergew(raw[s][3]);
        // prefetch pw chunk c+2 into freed slot
        {
            int pc = (c + 2 < cEnd) ? (c + 2) : (cEnd - 1);
#pragma unroll
            for (int i = 0; i < 4; ++i) raw[s][i] = pwq[pc * 4 + i];
        }
        // stage B chunk c+2 (from bv regs), prefetch chunk c+3
        {
            int wslot = (c + 2) & 3;
            *reinterpret_cast<uint4*>(sB + wslot * BBUF + bk * BROW + bseg * 32)      = bv0;
            *reinterpret_cast<uint4*>(sB + wslot * BBUF + bk * BROW + bseg * 32 + 16) = bv1;
            int bc = (c + 3 < cEnd) ? (c + 3) : (cEnd - 1);
            bv0 = *reinterpret_cast<const uint4*>(xtb + (size_t)(bc * 64 + bk) * 64 + bseg * 32);
            bv1 = *reinterpret_cast<const uint4*>(xtb + (size_t)(bc * 64 + bk) * 64 + bseg * 32 + 16);
        }
        __syncthreads();

        // compute on sBB[c&3] and wk*
        const uint32_t bbase = sB0 + (uint32_t)(c & 3) * BBUF + ld_off;
        uint32_t wks[4] = { wk0, wk1, wk2, wk3 };
#pragma unroll
        for (int ks = 0; ks < 4; ++ks) {
            uint32_t b0, b1, b2, b3, b4, b5, b6, b7;
            ldsm4t(bbase + ks * (16 * BROW),      b0, b1, b2, b3);   // ntiles 0,1
            ldsm4t(bbase + ks * (16 * BROW) + 32, b4, b5, b6, b7);   // ntiles 2,3
            uint32_t wv = wks[ks];
            const int rb = lane >> 2;
#pragma unroll
            for (int af = 0; af < 2; ++af) {
                uint32_t wlo = (uint32_t)__shfl_sync(0xffffffffu, (int)wv, rb + af * 16);
                uint32_t whi = (uint32_t)__shfl_sync(0xffffffffu, (int)wv, rb + af * 16 + 8);
                uint32_t a0, a1, a2, a3;
                dec(wlo, sh, a0, a2);
                dec(whi, sh, a1, a3);
                mma16816(acc[af][0], a0, a1, a2, a3, b0, b1);
                mma16816(acc[af][1], a0, a1, a2, a3, b2, b3);
                mma16816(acc[af][2], a0, a1, a2, a3, b4, b5);
                mma16816(acc[af][3], a0, a1, a2, a3, b6, b7);
            }
        }
    }

    // ---- epilogue: write raw fp32 partials for this K-quarter ----
    float* pout = g_part + (size_t)sq * NB * U_DIM;
    const int rb = lane >> 2;
#pragma unroll
    for (int af = 0; af < 2; ++af) {
        const int ua = u0 + wid * 32 + af * 16 + rb;
        const int ub = ua + 8;
#pragma unroll
        for (int nt = 0; nt < 4; ++nt) {
            const int n0 = nt * 8 + (lane & 3) * 2;
            pout[(size_t)n0 * U_DIM + ua]       = acc[af][nt][0];
            pout[(size_t)(n0 + 1) * U_DIM + ua] = acc[af][nt][1];
            pout[(size_t)n0 * U_DIM + ub]       = acc[af][nt][2];
            pout[(size_t)(n0 + 1) * U_DIM + ub] = acc[af][nt][3];
        }
    }
}

// ===================== combine: sum partials, scale/bias/clip (float4) =====================
__global__ void __launch_bounds__(256)
combine_kernel(const float* __restrict__ scale,
               const float* __restrict__ bias,
               float* __restrict__ out) {
    int i4 = (blockIdx.x * blockDim.x + threadIdx.x) * 4;   // = n*U_DIM + u, u%4==0
    int u  = i4 % U_DIM;
    const float4 p0 = *reinterpret_cast<const float4*>(g_part + i4);
    const float4 p1 = *reinterpret_cast<const float4*>(g_part + (size_t)NB * U_DIM + i4);
    const float4 p2 = *reinterpret_cast<const float4*>(g_part + (size_t)2 * NB * U_DIM + i4);
    const float4 p3 = *reinterpret_cast<const float4*>(g_part + (size_t)3 * NB * U_DIM + i4);
    const float4 sc = *reinterpret_cast<const float4*>(scale + u);
    const float4 bi = *reinterpret_cast<const float4*>(bias + u);
    float4 r;
    r.x = fminf(fmaxf((p0.x + p1.x + p2.x + p3.x) * sc.x + bi.x, -CLIPV), CLIPV);
    r.y = fminf(fmaxf((p0.y + p1.y + p2.y + p3.y) * sc.y + bi.y, -CLIPV), CLIPV);
    r.z = fminf(fmaxf((p0.z + p1.z + p2.z + p3.z) * sc.z + bi.z, -CLIPV), CLIPV);
    r.w = fminf(fmaxf((p0.w + p1.w + p2.w + p3.w) * sc.w + bi.w, -CLIPV), CLIPV);
    *reinterpret_cast<float4*>(out + i4) = r;
}

// ===================== launch =====================
extern "C" void kernel_launch(void* const* d_in, const int* in_sizes, int n_in,
                              void* d_out, int out_size) {
    const float* x     = (const float*)d_in[0];
    const int*   pw    = (const int*)d_in[1];
    const float* scale = (const float*)d_in[2];
    const float* bias  = (const float*)d_in[3];
    float*       out   = (float*)d_out;

    xt_kernel<<<K_DIM / 32, 256>>>(x);
    ternary_hmma_kernel<<<NCTA_U * NSPLIT, 128>>>(pw);
    combine_kernel<<<(NB * U_DIM) / 1024, 256>>>(scale, bias, out);
}

// round 12
// speedup vs baseline: 2.0529x; 1.0144x over previous
#include <cuda_runtime.h>
#include <cuda_fp16.h>
#include <cstdint>

// ===================== problem constants =====================
#define U_DIM   14336
#define K_DIM   4096
#define NB      32
#define TILE_M  128
#define NCTA_U  (U_DIM / TILE_M)     // 112
#define NCHUNK  (K_DIM / 64)         // 64 chunks of 64 k-values
#define NSPLIT  4
#define NCHUNK_Q (NCHUNK / NSPLIT)   // 16 chunks per CTA
#define CLIPV   100.0f
// PRMT LUT bytes: crumb 0->0x00, 1->0x3C (+1 fp16 hi), 2->0xBC (-1), 3->0x00
#define HI_LUT  0x00BC3C00u

// x transposed to [K][N] fp16 (written by pre-kernel)
__device__ __half g_xt[K_DIM * NB];
// split-K fp32 partials: [split][n][u]
__device__ float  g_part[NSPLIT * NB * U_DIM];

// ===================== helpers =====================
__device__ __forceinline__ uint32_t prmt(uint32_t a, uint32_t b, uint32_t s) {
    uint32_t r; asm("prmt.b32 %0,%1,%2,%3;" : "=r"(r) : "r"(a), "r"(b), "r"(s)); return r;
}
__device__ __forceinline__ uint32_t smem_u32(const void* p) {
    uint32_t a;
    asm("{ .reg .u64 t; cvta.to.shared.u64 t, %1; cvt.u32.u64 %0, t; }" : "=r"(a) : "l"(p));
    return a;
}
// merge 4 int32 (one crumb-byte each, low byte) -> one 32-bit word of 16 crumbs
__device__ __forceinline__ uint32_t mergew(uint4 q) {
    return prmt(prmt(q.x, q.y, 0x0040), prmt(q.z, q.w, 0x0040), 0x5410);
}
// decode: from 16-crumb word w, lane's quad q=lane&3 (sh=4q) extract crumbs
// (2q,2q+1) -> lo (fp16x2) and (2q+8,2q+9) -> hi (fp16x2)
__device__ __forceinline__ void dec(uint32_t w, uint32_t sh, uint32_t& lo, uint32_t& hi) {
    uint32_t t   = w >> sh;
    uint32_t x   = t & 0x000F000Fu;
    uint32_t z   = x | (x << 2);
    uint32_t sel = (z & 0x33u) | ((z >> 8) & 0x3300u);
    uint32_t h   = prmt(HI_LUT, 0u, sel);   // bytes = hi-bytes of the 4 fp16 values
    lo = prmt(h, 0u, 0x1404u);              // {0,h0,0,h1}
    hi = prmt(h, 0u, 0x3424u);              // {0,h2,0,h3}
}
__device__ __forceinline__ void mma16816(float* c,
        uint32_t a0, uint32_t a1, uint32_t a2, uint32_t a3,
        uint32_t b0, uint32_t b1) {
    asm volatile(
        "mma.sync.aligned.m16n8k16.row.col.f32.f16.f16.f32 "
        "{%0,%1,%2,%3},{%4,%5,%6,%7},{%8,%9},{%0,%1,%2,%3};"
        : "+f"(c[0]), "+f"(c[1]), "+f"(c[2]), "+f"(c[3])
        : "r"(a0), "r"(a1), "r"(a2), "r"(a3), "r"(b0), "r"(b1));
}
__device__ __forceinline__ void ldsm4t(uint32_t addr,
        uint32_t& r0, uint32_t& r1, uint32_t& r2, uint32_t& r3) {
    asm volatile("ldmatrix.sync.aligned.m8n8.x4.trans.shared.b16 {%0,%1,%2,%3}, [%4];"
        : "=r"(r0), "=r"(r1), "=r"(r2), "=r"(r3) : "r"(addr));
}
// 16-byte async copy global -> shared (L1 bypass path not required; .ca is fine)
__device__ __forceinline__ void cp16(uint32_t saddr, const void* gptr) {
    asm volatile("cp.async.ca.shared.global [%0], [%1], 16;"
                 :: "r"(saddr), "l"(__cvta_generic_to_global(gptr)) : "memory");
}
#define CP_COMMIT() asm volatile("cp.async.commit_group;" ::: "memory")
#define CP_WAIT2()  asm volatile("cp.async.wait_group 2;"  ::: "memory")

// ===================== pre-kernel: x[N][K] f32 -> g_xt[K][N] f16 =====================
// grid 32, block 256: each CTA transposes a 128k x 32n tile; MLP=4 per thread
__global__ void __launch_bounds__(256)
xt_kernel(const float* __restrict__ x) {
    __shared__ __half s[128][33];
    const int k0  = blockIdx.x * 128;
    const int t   = threadIdx.x;
    const int n_r = t >> 3;              // 0..31
    const int kq  = (t & 7) * 4;         // 0,4,..,28
    float4 v[4];
#pragma unroll
    for (int sb = 0; sb < 4; ++sb)
        v[sb] = *reinterpret_cast<const float4*>(x + (size_t)n_r * K_DIM + k0 + sb * 32 + kq);
#pragma unroll
    for (int sb = 0; sb < 4; ++sb) {
        const int k = sb * 32 + kq;
        s[k + 0][n_r] = __float2half_rn(v[sb].x);
        s[k + 1][n_r] = __float2half_rn(v[sb].y);
        s[k + 2][n_r] = __float2half_rn(v[sb].z);
        s[k + 3][n_r] = __float2half_rn(v[sb].w);
    }
    __syncthreads();
    // write side: 128 rows x 64B = 512 16B segments; 2 per thread
#pragma unroll
    for (int e = 0; e < 2; ++e) {
        const int seg = t * 2 + e;
        const int k   = seg >> 2;
        const int n0  = (seg & 3) * 8;
        uint4 o;
        __half2* ph = reinterpret_cast<__half2*>(&o);
        ph[0] = __halves2half2(s[k][n0 + 0], s[k][n0 + 1]);
        ph[1] = __halves2half2(s[k][n0 + 2], s[k][n0 + 3]);
        ph[2] = __halves2half2(s[k][n0 + 4], s[k][n0 + 5]);
        ph[3] = __halves2half2(s[k][n0 + 6], s[k][n0 + 7]);
        *reinterpret_cast<uint4*>(g_xt + (size_t)(k0 + k) * NB + n0) = o;
    }
}

// ===================== main GEMM =====================
// 448 CTAs x 128 threads; CTA = (u-tile, K-quarter); 4 warps, each m32 x n32
// occupancy 4 -> grid 448 fits in ONE wave (148*4 = 592)
#define BROW 80          // padded bytes per k-row in smem B tile (64B data + 16 pad)
#define BBUF (64 * BROW) // 5120 B per ring slot

__global__ void __launch_bounds__(128, 4)
ternary_hmma_kernel(const int* __restrict__ pw) {
    __shared__ __align__(16) uint8_t sBB[4][BBUF];   // 20 KB ring of B tiles [k][n]

    const int tid  = threadIdx.x;
    const int lane = tid & 31;
    const int wid  = tid >> 5;
    const int bu   = blockIdx.x >> 2;        // u-tile index   (0..111)
    const int sq   = blockIdx.x & 3;         // K-quarter      (0..3)
    const int u0   = bu * TILE_M;
    const int c0   = sq * NCHUNK_Q;          // first chunk (multiple of 16 -> ring aligned)
    const int cEnd = c0 + NCHUNK_Q;
    const uint32_t sh = (lane & 3) * 4;

    // lane owns weight row u0 + wid*32 + lane
    const int urow = u0 + wid * 32 + lane;
    const uint4* pwq = reinterpret_cast<const uint4*>(pw + (size_t)urow * (K_DIM / 4));

    // B staging task: thread -> (k-row, 32B segment), via cp.async
    const int bk   = tid >> 1;
    const int bseg = tid & 1;
    const uint8_t* xtb = reinterpret_cast<const uint8_t*>(g_xt);
    const uint32_t sB0 = smem_u32(sBB);
    const uint32_t stg_s = sB0 + (uint32_t)(bk * BROW + bseg * 32);

    // ldmatrix per-lane offset: krow = lane&15, ntile-pair select = lane>>4
    const uint32_t ld_off = (uint32_t)((lane & 15) * BROW + (lane >> 4) * 16);

    float acc[2][4][4];
#pragma unroll
    for (int a = 0; a < 2; ++a)
#pragma unroll
        for (int t = 0; t < 4; ++t)
#pragma unroll
            for (int j = 0; j < 4; ++j) acc[a][t][j] = 0.0f;

    // ---- prologue: pw prefetch ring depth 2; cp.async-stage B chunks c0..c0+2 ----
    uint4 raw[2][4];
#pragma unroll
    for (int s = 0; s < 2; ++s)
#pragma unroll
        for (int i = 0; i < 4; ++i) raw[s][i] = pwq[(c0 + s) * 4 + i];

#pragma unroll
    for (int cc = 0; cc < 3; ++cc) {
        const uint8_t* g = xtb + (size_t)((c0 + cc) * 64 + bk) * 64 + bseg * 32;
        const uint32_t sdst = stg_s + (uint32_t)(cc * BBUF);
        cp16(sdst,      g);
        cp16(sdst + 16, g + 16);
        CP_COMMIT();
    }

    // ---- main loop over this CTA's 16 chunks ----
#pragma unroll 4
    for (int c = c0; c < cEnd; ++c) {
        const int s = c & 1;
        // merge current chunk's crumb words (row = lane)
        uint32_t wk0 = mergew(raw[s][0]);
        uint32_t wk1 = mergew(raw[s][1]);
        uint32_t wk2 = mergew(raw[s][2]);
        uint32_t wk3 = mergew(raw[s][3]);
        // prefetch pw chunk c+2 into freed slot
        {
            int pc = (c + 2 < cEnd) ? (c + 2) : (cEnd - 1);
#pragma unroll
            for (int i = 0; i < 4; ++i) raw[s][i] = pwq[pc * 4 + i];
        }

        // group for chunk c complete (<=2 outstanding), then barrier so the
        // recycled slot (c+3)&3 is no longer being read by any warp
        CP_WAIT2();
        __syncthreads();

        // stage chunk c+3 into freed slot (always commit to keep accounting)
        if (c + 3 < cEnd) {
            const uint8_t* g = xtb + (size_t)((c + 3) * 64 + bk) * 64 + bseg * 32;
            const uint32_t sdst = stg_s + (uint32_t)(((c + 3) & 3) * BBUF);
            cp16(sdst,      g);
            cp16(sdst + 16, g + 16);
        }
        CP_COMMIT();

        // compute on sBB[c&3] and wk*
        const uint32_t bbase = sB0 + (uint32_t)(c & 3) * BBUF + ld_off;
        uint32_t wks[4] = { wk0, wk1, wk2, wk3 };
#pragma unroll
        for (int ks = 0; ks < 4; ++ks) {
            uint32_t b0, b1, b2, b3, b4, b5, b6, b7;
            ldsm4t(bbase + ks * (16 * BROW),      b0, b1, b2, b3);   // ntiles 0,1
            ldsm4t(bbase + ks * (16 * BROW) + 32, b4, b5, b6, b7);   // ntiles 2,3
            uint32_t wv = wks[ks];
            const int rb = lane >> 2;
#pragma unroll
            for (int af = 0; af < 2; ++af) {
                uint32_t wlo = (uint32_t)__shfl_sync(0xffffffffu, (int)wv, rb + af * 16);
                uint32_t whi = (uint32_t)__shfl_sync(0xffffffffu, (int)wv, rb + af * 16 + 8);
                uint32_t a0, a1, a2, a3;
                dec(wlo, sh, a0, a2);
                dec(whi, sh, a1, a3);
                mma16816(acc[af][0], a0, a1, a2, a3, b0, b1);
                mma16816(acc[af][1], a0, a1, a2, a3, b2, b3);
                mma16816(acc[af][2], a0, a1, a2, a3, b4, b5);
                mma16816(acc[af][3], a0, a1, a2, a3, b6, b7);
            }
        }
    }

    // ---- epilogue: write raw fp32 partials for this K-quarter ----
    float* pout = g_part + (size_t)sq * NB * U_DIM;
    const int rb = lane >> 2;
#pragma unroll
    for (int af = 0; af < 2; ++af) {
        const int ua = u0 + wid * 32 + af * 16 + rb;
        const int ub = ua + 8;
#pragma unroll
        for (int nt = 0; nt < 4; ++nt) {
            const int n0 = nt * 8 + (lane & 3) * 2;
            pout[(size_t)n0 * U_DIM + ua]       = acc[af][nt][0];
            pout[(size_t)(n0 + 1) * U_DIM + ua] = acc[af][nt][1];
            pout[(size_t)n0 * U_DIM + ub]       = acc[af][nt][2];
            pout[(size_t)(n0 + 1) * U_DIM + ub] = acc[af][nt][3];
        }
    }
}

// ===================== combine: sum partials, scale/bias/clip (float4) =====================
__global__ void __launch_bounds__(256)
combine_kernel(const float* __restrict__ scale,
               const float* __restrict__ bias,
               float* __restrict__ out) {
    int i4 = (blockIdx.x * blockDim.x + threadIdx.x) * 4;   // = n*U_DIM + u, u%4==0
    int u  = i4 % U_DIM;
    const float4 p0 = *reinterpret_cast<const float4*>(g_part + i4);
    const float4 p1 = *reinterpret_cast<const float4*>(g_part + (size_t)NB * U_DIM + i4);
    const float4 p2 = *reinterpret_cast<const float4*>(g_part + (size_t)2 * NB * U_DIM + i4);
    const float4 p3 = *reinterpret_cast<const float4*>(g_part + (size_t)3 * NB * U_DIM + i4);
    const float4 sc = *reinterpret_cast<const float4*>(scale + u);
    const float4 bi = *reinterpret_cast<const float4*>(bias + u);
    float4 r;
    r.x = fminf(fmaxf((p0.x + p1.x + p2.x + p3.x) * sc.x + bi.x, -CLIPV), CLIPV);
    r.y = fminf(fmaxf((p0.y + p1.y + p2.y + p3.y) * sc.y + bi.y, -CLIPV), CLIPV);
    r.z = fminf(fmaxf((p0.z + p1.z + p2.z + p3.z) * sc.z + bi.z, -CLIPV), CLIPV);
    r.w = fminf(fmaxf((p0.w + p1.w + p2.w + p3.w) * sc.w + bi.w, -CLIPV), CLIPV);
    *reinterpret_cast<float4*>(out + i4) = r;
}

// ===================== launch =====================
extern "C" void kernel_launch(void* const* d_in, const int* in_sizes, int n_in,
                              void* d_out, int out_size) {
    const float* x     = (const float*)d_in[0];
    const int*   pw    = (const int*)d_in[1];
    const float* scale = (const float*)d_in[2];
    const float* bias  = (const float*)d_in[3];
    float*       out   = (float*)d_out;

    xt_kernel<<<K_DIM / 128, 256>>>(x);
    ternary_hmma_kernel<<<NCTA_U * NSPLIT, 128>>>(pw);
    combine_kernel<<<(NB * U_DIM) / 1024, 256>>>(scale, bias, out);
}